// round 1
// baseline (speedup 1.0000x reference)
#include <cuda_runtime.h>
#include <math.h>

#define BB   32
#define EE   8
#define HW   196
#define EPS  1e-5f

// ---------------- scratch (device globals; no runtime allocation) -------------
__device__ float g_pooled[BB * 1024];
__device__ float g_rw[BB * EE];
__device__ float g_cw[BB * 256 * 256 * 9];   // 75.5 MB, reused per stage (max size = stage 2)
__device__ float g_out1[BB * 256 * HW];
__device__ float g_out2[BB * 256 * HW];

// ---------------- global average pool: one warp per (b, c) --------------------
__global__ void pool_kernel(const float* __restrict__ X, float* __restrict__ P, int total_rows)
{
    int warp = (blockIdx.x * blockDim.x + threadIdx.x) >> 5;
    int lane = threadIdx.x & 31;
    if (warp >= total_rows) return;
    const float* row = X + (size_t)warp * HW;
    float s = 0.f;
    for (int i = lane; i < HW; i += 32) s += row[i];
    #pragma unroll
    for (int o = 16; o; o >>= 1) s += __shfl_down_sync(0xffffffffu, s, o);
    if (lane == 0) P[warp] = s * (1.0f / HW);
}

// ---------------- routing: block per b, warp per expert -----------------------
__global__ void route_kernel(const float* __restrict__ P, const float* __restrict__ Wr,
                             const float* __restrict__ br, float* __restrict__ RW, int C)
{
    int b    = blockIdx.x;
    int e    = threadIdx.x >> 5;
    int lane = threadIdx.x & 31;
    float s = 0.f;
    for (int c = lane; c < C; c += 32) s += P[b * C + c] * Wr[c * EE + e];
    #pragma unroll
    for (int o = 16; o; o >>= 1) s += __shfl_down_sync(0xffffffffu, s, o);
    if (lane == 0) {
        float t = s + br[e];
        RW[b * EE + e] = 1.0f / (1.0f + expf(-t));
    }
}

// ---------------- expert combine: cw[b] = sum_e rw[b,e] * w[e] ---------------
// Each thread owns one float4 of the weight tensor, reads 8 experts once,
// loops over all 32 samples (w read exactly once from L2; writes are streaming).
__global__ void combine_kernel(const float* __restrict__ Wexp, const float* __restrict__ RW,
                               float* __restrict__ CW, int Wsz4)
{
    __shared__ float rws[BB * EE];
    if (threadIdx.x < BB * EE) rws[threadIdx.x] = RW[threadIdx.x];
    __syncthreads();
    int idx = blockIdx.x * blockDim.x + threadIdx.x;
    if (idx >= Wsz4) return;
    float4 we[EE];
    #pragma unroll
    for (int e = 0; e < EE; e++) we[e] = ((const float4*)Wexp)[(size_t)e * Wsz4 + idx];
    #pragma unroll 4
    for (int b = 0; b < BB; b++) {
        float4 acc = make_float4(0.f, 0.f, 0.f, 0.f);
        #pragma unroll
        for (int e = 0; e < EE; e++) {
            float r = rws[b * EE + e];
            acc.x = fmaf(r, we[e].x, acc.x);
            acc.y = fmaf(r, we[e].y, acc.y);
            acc.z = fmaf(r, we[e].z, acc.z);
            acc.w = fmaf(r, we[e].w, acc.w);
        }
        ((float4*)CW)[(size_t)b * Wsz4 + idx] = acc;
    }
}

// ---------------- cond conv as per-sample GEMM + fused BN/ReLU(/residual) ----
// C[b][M x 196] = W[b][M x K] * X[b][K x 196]
// Block: 224 threads = 8 m-groups x 28 n-groups. Thread tile: MR(=4) x 7.
// M_TILE = 32, KT = 16. 3x3 conv decodes im2col during the Xs smem fill.
template<int MR, bool CONV3x3, bool RESID>
__global__ void __launch_bounds__(224)
cond_conv_kernel(const float* __restrict__ X, const float* __restrict__ W,
                 const float* __restrict__ gam, const float* __restrict__ bet,
                 const float* __restrict__ mu,  const float* __restrict__ var,
                 const float* __restrict__ resid, float* __restrict__ Out,
                 int M_total, int K)
{
    constexpr int MT = MR * 8;     // rows per block
    constexpr int KT = 16;

    const int b     = blockIdx.y;
    const int mbase = blockIdx.x * MT;
    const int tid   = threadIdx.x;
    const int my    = tid / 28;          // 0..7
    const int ny    = tid % 28;          // 0..27
    const int n0    = ny * 7;

    __shared__ float Ws[KT][MT + 1];
    __shared__ float Xs[KT][HW];

    float acc[MR][7];
    #pragma unroll
    for (int i = 0; i < MR; i++)
        #pragma unroll
        for (int j = 0; j < 7; j++) acc[i][j] = 0.f;

    const float* Wb = W + (size_t)b * M_total * K;
    const int Cin   = CONV3x3 ? (K / 9) : K;
    const float* Xb = X + (size_t)b * Cin * HW;

    for (int k0 = 0; k0 < K; k0 += KT) {
        // W tile (coalesced along K)
        for (int idx = tid; idx < KT * MT; idx += 224) {
            int m = idx >> 4, k = idx & 15;
            Ws[k][m] = Wb[(size_t)(mbase + m) * K + (k0 + k)];
        }
        // X tile
        if (!CONV3x3) {
            for (int idx = tid; idx < KT * HW; idx += 224) {
                int k = idx / HW, n = idx - k * HW;
                Xs[k][n] = Xb[(size_t)(k0 + k) * HW + n];
            }
        } else {
            for (int idx = tid; idx < KT * HW; idx += 224) {
                int k  = idx / HW, n = idx - k * HW;
                int kk = k0 + k;
                int c  = kk / 9, r = kk - c * 9;
                int dy = r / 3 - 1, dx = r - (r / 3) * 3 - 1;
                int oy = n / 14,  ox = n - oy * 14;
                int iy = oy + dy, ix = ox + dx;
                float v = 0.f;
                if (iy >= 0 && iy < 14 && ix >= 0 && ix < 14)
                    v = Xb[(size_t)c * HW + iy * 14 + ix];
                Xs[k][n] = v;
            }
        }
        __syncthreads();

        #pragma unroll
        for (int k = 0; k < KT; k++) {
            float wr[MR], xr[7];
            #pragma unroll
            for (int i = 0; i < MR; i++) wr[i] = Ws[k][my * MR + i];
            #pragma unroll
            for (int j = 0; j < 7; j++) xr[j] = Xs[k][n0 + j];
            #pragma unroll
            for (int i = 0; i < MR; i++)
                #pragma unroll
                for (int j = 0; j < 7; j++)
                    acc[i][j] = fmaf(wr[i], xr[j], acc[i][j]);
        }
        __syncthreads();
    }

    // epilogue: BN (+residual) + ReLU
    #pragma unroll
    for (int i = 0; i < MR; i++) {
        int row = mbase + my * MR + i;
        float inv  = rsqrtf(var[row] + EPS) * gam[row];
        float beta = bet[row] - mu[row] * inv;
        size_t obase = (size_t)b * M_total * HW + (size_t)row * HW + n0;
        #pragma unroll
        for (int j = 0; j < 7; j++) {
            float v = fmaf(acc[i][j], inv, beta);
            if (RESID) v += resid[obase + j];
            Out[obase + j] = fmaxf(v, 0.f);
        }
    }
}

// ------------------------------------------------------------------------------
extern "C" void kernel_launch(void* const* d_in, const int* in_sizes, int n_in,
                              void* d_out, int out_size)
{
    const float* x    = (const float*)d_in[0];
    const float* w1   = (const float*)d_in[1];
    const float* w2   = (const float*)d_in[2];
    const float* w3   = (const float*)d_in[3];
    const float* r1w  = (const float*)d_in[4];
    const float* r1b  = (const float*)d_in[5];
    const float* r2w  = (const float*)d_in[6];
    const float* r2b  = (const float*)d_in[7];
    const float* r3w  = (const float*)d_in[8];
    const float* r3b  = (const float*)d_in[9];
    const float* bn1g = (const float*)d_in[10];
    const float* bn1b = (const float*)d_in[11];
    const float* bn1m = (const float*)d_in[12];
    const float* bn1v = (const float*)d_in[13];
    const float* bn2g = (const float*)d_in[14];
    const float* bn2b = (const float*)d_in[15];
    const float* bn2m = (const float*)d_in[16];
    const float* bn2v = (const float*)d_in[17];
    const float* bn3g = (const float*)d_in[18];
    const float* bn3b = (const float*)d_in[19];
    const float* bn3m = (const float*)d_in[20];
    const float* bn3v = (const float*)d_in[21];
    float* out = (float*)d_out;

    float *pooled, *rw, *cw, *o1, *o2;
    cudaGetSymbolAddress((void**)&pooled, g_pooled);
    cudaGetSymbolAddress((void**)&rw,     g_rw);
    cudaGetSymbolAddress((void**)&cw,     g_cw);
    cudaGetSymbolAddress((void**)&o1,     g_out1);
    cudaGetSymbolAddress((void**)&o2,     g_out2);

    // ---- stage 1: route on x, combine w1, 1x1 conv (K=1024 -> M=256) ----
    pool_kernel<<<(BB * 1024 * 32 + 255) / 256, 256>>>(x, pooled, BB * 1024);
    route_kernel<<<BB, 256>>>(pooled, r1w, r1b, rw, 1024);
    {
        int Wsz4 = (256 * 1024) / 4;   // 65536
        combine_kernel<<<Wsz4 / 256, 256>>>(w1, rw, cw, Wsz4);
    }
    cond_conv_kernel<4, false, false><<<dim3(256 / 32, BB), 224>>>(
        x, cw, bn1g, bn1b, bn1m, bn1v, nullptr, o1, 256, 1024);

    // ---- stage 2: route on out1, combine w2, 3x3 conv (K=2304 -> M=256) ----
    pool_kernel<<<(BB * 256 * 32 + 255) / 256, 256>>>(o1, pooled, BB * 256);
    route_kernel<<<BB, 256>>>(pooled, r2w, r2b, rw, 256);
    {
        int Wsz4 = (256 * 256 * 9) / 4;  // 147456
        combine_kernel<<<Wsz4 / 256, 256>>>(w2, rw, cw, Wsz4);
    }
    cond_conv_kernel<4, true, false><<<dim3(256 / 32, BB), 224>>>(
        o1, cw, bn2g, bn2b, bn2m, bn2v, nullptr, o2, 256, 2304);

    // ---- stage 3: route on out2, combine w3, 1x1 conv (K=256 -> M=1024) + resid ----
    pool_kernel<<<(BB * 256 * 32 + 255) / 256, 256>>>(o2, pooled, BB * 256);
    route_kernel<<<BB, 256>>>(pooled, r3w, r3b, rw, 256);
    {
        int Wsz4 = (1024 * 256) / 4;    // 65536
        combine_kernel<<<Wsz4 / 256, 256>>>(w3, rw, cw, Wsz4);
    }
    cond_conv_kernel<4, false, true><<<dim3(1024 / 32, BB), 224>>>(
        o2, cw, bn3g, bn3b, bn3m, bn3v, x, out, 1024, 256);
}

// round 2
// speedup vs baseline: 2.1037x; 2.1037x over previous
#include <cuda_runtime.h>
#include <math.h>

#define BB   32
#define EE   8
#define HW   196
#define EPS  1e-5f

#define MT       64
#define KT       16
#define NTHREADS 224
#define WS_STR   66    // padded row stride for Ws: conflict-free STS, 8B-aligned rows

typedef unsigned long long ull;

// ---------------- scratch (device globals; no runtime allocation) -------------
__device__ float g_pooled[BB * 1024];
__device__ float g_rw[BB * EE];
__device__ float g_cw[BB * 256 * 256 * 9];      // combined weights (max = stage 2)
__device__ float g_xcol[BB * 2304 * HW];        // im2col buffer for stage 2
__device__ float g_out1[BB * 256 * HW];
__device__ float g_out2[BB * 256 * HW];
__device__ float g_part[2 * BB * 256 * HW];     // split-K partials (2 splits, M<=256)

// ---------------- f32x2 helpers -----------------------------------------------
__device__ __forceinline__ ull ffma2(ull a, ull b, ull c) {
    ull d; asm("fma.rn.f32x2 %0, %1, %2, %3;" : "=l"(d) : "l"(a), "l"(b), "l"(c));
    return d;
}
__device__ __forceinline__ ull pack2(float lo, float hi) {
    ull d; asm("mov.b64 %0, {%1,%2};" : "=l"(d) : "f"(lo), "f"(hi));
    return d;
}
__device__ __forceinline__ void unpack2(ull v, float& lo, float& hi) {
    asm("mov.b64 {%0,%1}, %2;" : "=f"(lo), "=f"(hi) : "l"(v));
}
__device__ __forceinline__ void cp16(void* smem, const void* g) {
    unsigned s = (unsigned)__cvta_generic_to_shared(smem);
    asm volatile("cp.async.cg.shared.global [%0], [%1], 16;" :: "r"(s), "l"(g));
}
#define CP_COMMIT() asm volatile("cp.async.commit_group;" ::: "memory")

// ---------------- global average pool: one warp per (b, c) --------------------
__global__ void pool_kernel(const float* __restrict__ X, float* __restrict__ P, int total_rows)
{
    int warp = (blockIdx.x * blockDim.x + threadIdx.x) >> 5;
    int lane = threadIdx.x & 31;
    if (warp >= total_rows) return;
    const float* row = X + (size_t)warp * HW;
    float s = 0.f;
    for (int i = lane; i < HW; i += 32) s += row[i];
    #pragma unroll
    for (int o = 16; o; o >>= 1) s += __shfl_down_sync(0xffffffffu, s, o);
    if (lane == 0) P[warp] = s * (1.0f / HW);
}

// ---------------- routing: block per b, warp per expert -----------------------
__global__ void route_kernel(const float* __restrict__ P, const float* __restrict__ Wr,
                             const float* __restrict__ br, float* __restrict__ RW, int C)
{
    int b    = blockIdx.x;
    int e    = threadIdx.x >> 5;
    int lane = threadIdx.x & 31;
    float s = 0.f;
    for (int c = lane; c < C; c += 32) s += P[b * C + c] * Wr[c * EE + e];
    #pragma unroll
    for (int o = 16; o; o >>= 1) s += __shfl_down_sync(0xffffffffu, s, o);
    if (lane == 0) {
        float t = s + br[e];
        RW[b * EE + e] = 1.0f / (1.0f + expf(-t));
    }
}

// ---------------- expert combine: cw[b] = sum_e rw[b,e] * w[e] ---------------
__global__ void combine_kernel(const float* __restrict__ Wexp, const float* __restrict__ RW,
                               float* __restrict__ CW, int Wsz4)
{
    __shared__ float rws[BB * EE];
    if (threadIdx.x < BB * EE) rws[threadIdx.x] = RW[threadIdx.x];
    __syncthreads();
    int idx = blockIdx.x * blockDim.x + threadIdx.x;
    if (idx >= Wsz4) return;
    float4 we[EE];
    #pragma unroll
    for (int e = 0; e < EE; e++) we[e] = ((const float4*)Wexp)[(size_t)e * Wsz4 + idx];
    #pragma unroll 4
    for (int b = 0; b < BB; b++) {
        float4 acc = make_float4(0.f, 0.f, 0.f, 0.f);
        #pragma unroll
        for (int e = 0; e < EE; e++) {
            float r = rws[b * EE + e];
            acc.x = fmaf(r, we[e].x, acc.x);
            acc.y = fmaf(r, we[e].y, acc.y);
            acc.z = fmaf(r, we[e].z, acc.z);
            acc.w = fmaf(r, we[e].w, acc.w);
        }
        ((float4*)CW)[(size_t)b * Wsz4 + idx] = acc;
    }
}

// ---------------- im2col for 3x3 (pad=1) conv: X[B,256,196] -> Xc[B,2304,196] -
__global__ void im2col_kernel(const float* __restrict__ X, float* __restrict__ Xc, int total)
{
    int idx = blockIdx.x * blockDim.x + threadIdx.x;
    if (idx >= total) return;
    int n  = idx % HW;
    int t  = idx / HW;
    int kk = t % 2304;
    int b  = t / 2304;
    int c  = kk / 9, r = kk - 9 * c;
    int dy = r / 3 - 1, dx = r - (r / 3) * 3 - 1;
    int oy = n / 14,  ox = n - 14 * oy;
    int iy = oy + dy, ix = ox + dx;
    float v = 0.f;
    if ((unsigned)iy < 14u && (unsigned)ix < 14u)
        v = X[((size_t)b * 256 + c) * HW + iy * 14 + ix];
    Xc[idx] = v;
}

// ---------------- main GEMM: C[b][64 x 196] tile, f32x2 FMA, double-buffered --
// Thread layout: my=tid/28 (8 m-groups), ny=tid%28. Per-thread tile: 8m x 7n,
// m packed in f32x2 pairs, n strided by 28 (coalesced epilogue stores).
template<bool FUSE>
__global__ void __launch_bounds__(NTHREADS, 2)
gemm_kernel(const float* __restrict__ Xc, const float* __restrict__ CW,
            float* __restrict__ dst,
            const float* __restrict__ gam, const float* __restrict__ bet,
            const float* __restrict__ mu,  const float* __restrict__ var,
            const float* __restrict__ resid,
            int M_total, int K, int Kc)
{
    __shared__ __align__(16) float Xs[2][KT][HW];
    __shared__ __align__(16) float Ws[2][KT][WS_STR];

    const int b     = blockIdx.z;
    const int split = blockIdx.y;
    const int mbase = blockIdx.x * MT;
    const int tid   = threadIdx.x;
    const int my    = tid / 28;
    const int ny    = tid % 28;
    const int kbeg  = split * Kc;
    const int nk    = Kc / KT;

    const float* Xb = Xc + ((size_t)b * K + kbeg) * HW;
    const float* Wb = CW + ((size_t)b * M_total + mbase) * K + kbeg;

    ull acc[4][7];
    #pragma unroll
    for (int p = 0; p < 4; p++)
        #pragma unroll
        for (int j = 0; j < 7; j++) acc[p][j] = 0ULL;

    float wst[5];

    // ---- loaders ----
    auto loadX = [&](int kt, int buf) {
        const float* src = Xb + (size_t)kt * KT * HW;
        #pragma unroll
        for (int i = 0; i < 4; i++) {
            int c = tid + i * NTHREADS;           // 784 chunks of 16B
            if (c < (KT * HW) / 4) {
                int k = c / 49, ch = c - 49 * k;
                cp16(&Xs[buf][k][ch * 4], src + (size_t)k * HW + ch * 4);
            }
        }
    };
    auto loadW_g = [&](int kt, float* wr) {
        const float* src = Wb + (size_t)kt * KT;
        #pragma unroll
        for (int i = 0; i < 5; i++) {
            int idx = tid + i * NTHREADS;
            if (idx < MT * KT) {
                int m = idx >> 4, k = idx & 15;
                wr[i] = src[(size_t)m * K + k];
            }
        }
    };
    auto storeW_s = [&](int buf, const float* wr) {
        #pragma unroll
        for (int i = 0; i < 5; i++) {
            int idx = tid + i * NTHREADS;
            if (idx < MT * KT) {
                int m = idx >> 4, k = idx & 15;
                Ws[buf][k][m] = wr[i];
            }
        }
    };

    // ---- pipelined mainloop ----
    loadX(0, 0); CP_COMMIT();
    loadW_g(0, wst);
    storeW_s(0, wst);

    for (int kt = 0; kt < nk; kt++) {
        const int cur = kt & 1, nxt = cur ^ 1;
        const bool has = (kt + 1 < nk);
        if (has) { loadX(kt + 1, nxt); CP_COMMIT(); loadW_g(kt + 1, wst); }
        if (has) asm volatile("cp.async.wait_group 1;" ::: "memory");
        else     asm volatile("cp.async.wait_group 0;" ::: "memory");
        __syncthreads();

        #pragma unroll
        for (int k = 0; k < KT; k++) {
            ull w[4], xx[7];
            #pragma unroll
            for (int p = 0; p < 4; p++)
                w[p] = *(const ull*)&Ws[cur][k][my * 8 + 2 * p];
            #pragma unroll
            for (int j = 0; j < 7; j++) {
                float xv = Xs[cur][k][ny + 28 * j];
                xx[j] = pack2(xv, xv);
            }
            #pragma unroll
            for (int p = 0; p < 4; p++)
                #pragma unroll
                for (int j = 0; j < 7; j++)
                    acc[p][j] = ffma2(w[p], xx[j], acc[p][j]);
        }
        if (has) storeW_s(nxt, wst);
        __syncthreads();
    }

    // ---- epilogue ----
    if (FUSE) {
        #pragma unroll
        for (int p = 0; p < 4; p++) {
            int r0 = mbase + my * 8 + 2 * p;
            float i0 = rsqrtf(var[r0]     + EPS) * gam[r0];
            float b0 = bet[r0]     - mu[r0]     * i0;
            float i1 = rsqrtf(var[r0 + 1] + EPS) * gam[r0 + 1];
            float b1 = bet[r0 + 1] - mu[r0 + 1] * i1;
            size_t o0 = ((size_t)b * M_total + r0) * HW;
            #pragma unroll
            for (int j = 0; j < 7; j++) {
                float lo, hi; unpack2(acc[p][j], lo, hi);
                int n = ny + 28 * j;
                float v0 = fmaf(lo, i0, b0) + resid[o0 + n];
                float v1 = fmaf(hi, i1, b1) + resid[o0 + HW + n];
                dst[o0 + n]      = fmaxf(v0, 0.f);
                dst[o0 + HW + n] = fmaxf(v1, 0.f);
            }
        }
    } else {
        #pragma unroll
        for (int p = 0; p < 4; p++) {
            int r0 = mbase + my * 8 + 2 * p;
            size_t o0 = (((size_t)split * BB + b) * M_total + r0) * HW;
            #pragma unroll
            for (int j = 0; j < 7; j++) {
                float lo, hi; unpack2(acc[p][j], lo, hi);
                int n = ny + 28 * j;
                dst[o0 + n]      = lo;
                dst[o0 + HW + n] = hi;
            }
        }
    }
}

// ---------------- split-K reduce + BN + ReLU (2 splits) -----------------------
__global__ void reduce_bn_relu(const float* __restrict__ Part, float* __restrict__ Out,
                               const float* __restrict__ gam, const float* __restrict__ bet,
                               const float* __restrict__ mu,  const float* __restrict__ var,
                               int M, int total)
{
    int idx = blockIdx.x * blockDim.x + threadIdx.x;
    if (idx >= total) return;
    int row = (idx / HW) % M;
    float s = Part[idx] + Part[(size_t)total + idx];
    float inv = rsqrtf(var[row] + EPS) * gam[row];
    Out[idx] = fmaxf(fmaf(s, inv, bet[row] - mu[row] * inv), 0.f);
}

// ------------------------------------------------------------------------------
extern "C" void kernel_launch(void* const* d_in, const int* in_sizes, int n_in,
                              void* d_out, int out_size)
{
    const float* x    = (const float*)d_in[0];
    const float* w1   = (const float*)d_in[1];
    const float* w2   = (const float*)d_in[2];
    const float* w3   = (const float*)d_in[3];
    const float* r1w  = (const float*)d_in[4];
    const float* r1b  = (const float*)d_in[5];
    const float* r2w  = (const float*)d_in[6];
    const float* r2b  = (const float*)d_in[7];
    const float* r3w  = (const float*)d_in[8];
    const float* r3b  = (const float*)d_in[9];
    const float* bn1g = (const float*)d_in[10];
    const float* bn1b = (const float*)d_in[11];
    const float* bn1m = (const float*)d_in[12];
    const float* bn1v = (const float*)d_in[13];
    const float* bn2g = (const float*)d_in[14];
    const float* bn2b = (const float*)d_in[15];
    const float* bn2m = (const float*)d_in[16];
    const float* bn2v = (const float*)d_in[17];
    const float* bn3g = (const float*)d_in[18];
    const float* bn3b = (const float*)d_in[19];
    const float* bn3m = (const float*)d_in[20];
    const float* bn3v = (const float*)d_in[21];
    float* out = (float*)d_out;

    float *pooled, *rw, *cw, *xcol, *o1, *o2, *part;
    cudaGetSymbolAddress((void**)&pooled, g_pooled);
    cudaGetSymbolAddress((void**)&rw,     g_rw);
    cudaGetSymbolAddress((void**)&cw,     g_cw);
    cudaGetSymbolAddress((void**)&xcol,   g_xcol);
    cudaGetSymbolAddress((void**)&o1,     g_out1);
    cudaGetSymbolAddress((void**)&o2,     g_out2);
    cudaGetSymbolAddress((void**)&part,   g_part);

    const int OUT1 = BB * 256 * HW;   // 1,605,632

    // ---- stage 1: 1x1 conv, K=1024 -> M=256, split-K=2 ----
    pool_kernel<<<(BB * 1024 * 32 + 255) / 256, 256>>>(x, pooled, BB * 1024);
    route_kernel<<<BB, 256>>>(pooled, r1w, r1b, rw, 1024);
    combine_kernel<<<(256 * 1024 / 4) / 256, 256>>>(w1, rw, cw, 256 * 1024 / 4);
    gemm_kernel<false><<<dim3(256 / MT, 2, BB), NTHREADS>>>(
        x, cw, part, nullptr, nullptr, nullptr, nullptr, nullptr, 256, 1024, 512);
    reduce_bn_relu<<<(OUT1 + 255) / 256, 256>>>(part, o1, bn1g, bn1b, bn1m, bn1v, 256, OUT1);

    // ---- stage 2: 3x3 conv via im2col, K=2304 -> M=256, split-K=2 ----
    pool_kernel<<<(BB * 256 * 32 + 255) / 256, 256>>>(o1, pooled, BB * 256);
    route_kernel<<<BB, 256>>>(pooled, r2w, r2b, rw, 256);
    combine_kernel<<<(256 * 2304 / 4) / 256, 256>>>(w2, rw, cw, 256 * 2304 / 4);
    {
        int total = BB * 2304 * HW;
        im2col_kernel<<<(total + 255) / 256, 256>>>(o1, xcol, total);
    }
    gemm_kernel<false><<<dim3(256 / MT, 2, BB), NTHREADS>>>(
        xcol, cw, part, nullptr, nullptr, nullptr, nullptr, nullptr, 256, 2304, 1152);
    reduce_bn_relu<<<(OUT1 + 255) / 256, 256>>>(part, o2, bn2g, bn2b, bn2m, bn2v, 256, OUT1);

    // ---- stage 3: 1x1 conv, K=256 -> M=1024, fused BN+resid+ReLU ----
    pool_kernel<<<(BB * 256 * 32 + 255) / 256, 256>>>(o2, pooled, BB * 256);
    route_kernel<<<BB, 256>>>(pooled, r3w, r3b, rw, 256);
    combine_kernel<<<(1024 * 256 / 4) / 256, 256>>>(w3, rw, cw, 1024 * 256 / 4);
    gemm_kernel<true><<<dim3(1024 / MT, 1, BB), NTHREADS>>>(
        o2, cw, out, bn3g, bn3b, bn3m, bn3v, x, 1024, 256, 256);
}